// round 16
// baseline (speedup 1.0000x reference)
#include <cuda_runtime.h>
#include <cuda_fp16.h>
#include <math.h>
#include <stdint.h>

#define CIN 64
#define NGRP 100
#define HID 256
#define BB 4
#define HH 112
#define H2 224
#define QQ 50176
#define MTOT (BB*QQ)   // 200704

typedef unsigned long long ull;

__device__ __forceinline__ void cpa16(void* dst, const void* src) {
    unsigned d = (unsigned)__cvta_generic_to_shared(dst);
    asm volatile("cp.async.cg.shared.global [%0], [%1], 16;" :: "r"(d), "l"(src));
}
__device__ __forceinline__ void cpa16z(void* dst, const void* src, int sz) {
    unsigned d = (unsigned)__cvta_generic_to_shared(dst);
    asm volatile("cp.async.cg.shared.global [%0], [%1], 16, %2;" :: "r"(d), "l"(src), "r"(sz));
}
__device__ __forceinline__ void ldsm4(uint32_t& r0, uint32_t& r1, uint32_t& r2, uint32_t& r3, uint32_t a) {
    asm volatile("ldmatrix.sync.aligned.m8n8.x4.shared.b16 {%0,%1,%2,%3}, [%4];"
        : "=r"(r0), "=r"(r1), "=r"(r2), "=r"(r3) : "r"(a));
}
__device__ __forceinline__ void mma16816(float* c, uint32_t a0, uint32_t a1, uint32_t a2, uint32_t a3,
                                         uint32_t b0, uint32_t b1) {
    asm volatile("mma.sync.aligned.m16n8k16.row.col.f32.f16.f16.f32 "
        "{%0,%1,%2,%3},{%4,%5,%6,%7},{%8,%9},{%0,%1,%2,%3};"
        : "+f"(c[0]), "+f"(c[1]), "+f"(c[2]), "+f"(c[3])
        : "r"(a0), "r"(a1), "r"(a2), "r"(a3), "r"(b0), "r"(b1));
}

// ---------------- scratch -----------------------------------------------------
__device__ __align__(16) __half g_f16[(size_t)BB*HH*HH*64];   // feat NHWC fp16
__device__ __align__(16) __half g_h16[(size_t)BB*HH*HH*64];   // conv112 out NHWC fp16
__device__ float g_wstat[49*4];
__device__ int   g_ctr;
__device__ float g_ktw[49*196];
__device__ __align__(16) __half g_gfh[(size_t)BB*H2*H2*64];    // gfeat NHWC fp16
__device__ __align__(16) __half g_coefh[(size_t)BB*H2*H2*HID]; // coef fp16
__device__ __align__(16) __half g_freqh[(size_t)BB*H2*H2*HID]; // freq fp16
__device__ __align__(16) __half g_X0h[(size_t)MTOT*HID];
__device__ __align__(16) __half g_X1h[(size_t)MTOT*HID];
__device__ __align__(16) unsigned char g_cw[(size_t)2*2*9*16384];  // conv224 weights
__device__ __align__(16) unsigned char g_cw1[(size_t)9*8192];      // conv112 weights
__device__ __align__(16) __half g_Wh[2][65536];

// ------- prep: feat NCHW->NHWC fp16, pack conv112 + MLP weights, zero stats ---
__global__ void feat_prep(const float* __restrict__ feat,
                          const float* __restrict__ cls_w1,
                          const float* __restrict__ w1, const float* __restrict__ w2) {
    int gid = blockIdx.x*256 + threadIdx.x;
    if (blockIdx.x == 0 && threadIdx.x < 196) g_wstat[threadIdx.x] = 0.f;
    if (gid < BB*HH*HH*64) {
        int c = gid & 63; int e = gid >> 6;
        int x = e % HH; e /= HH; int y = e % HH; int b = e / HH;
        g_f16[gid] = __float2half(feat[(((size_t)b*64 + c)*HH + y)*HH + x]);
    }
    if (gid < 36864) {
        int ci = gid & 63; int t = gid >> 6;
        int co = t & 63; int tap = t >> 6;
        float v = cls_w1[(size_t)co*576 + ci*9 + tap];
        uint32_t off = (uint32_t)co*128 + (((uint32_t)(ci>>3)*16) ^ (((uint32_t)co&7)<<4)) + (ci&7)*2;
        *(__half*)(g_cw1 + (size_t)tap*8192 + off) = __float2half(v);
    }
    if (gid < 131072) {
        int l = gid >> 16; int e = gid & 65535;
        const float* W = l ? w2 : w1;
        g_Wh[l][e] = __float2half(W[e]);
    }
}

// ---------------- conv3x3 64->64 @112 via mma.sync (all weights resident) -----
#define C1_WBASE 41472
#define C1_SMEM  (41472 + 9*8192)   // 115200

__global__ void __launch_bounds__(512, 1) conv112t(const float* __restrict__ bias) {
    extern __shared__ __align__(16) char smc[];
    __shared__ float sbias[64];
    uint32_t sb;
    asm("{ .reg .u64 t; cvta.to.shared.u64 t, %1; cvt.u32.u64 %0, t; }" : "=r"(sb) : "l"(smc));
    int tid = threadIdx.x, wid = tid >> 5, lane = tid & 31;
    int bt = blockIdx.x, b = blockIdx.z;
    int row0 = (bt/7)*16, col0 = (bt%7)*16;
    int wm = wid >> 1, wn = wid & 1;
    int nb = wn*32;

    int lr8  = lane & 7;
    int a_mh = (lane >> 3) & 1;
    int a_jh = (lane >> 4) & 1;
    int b_jh = (lane >> 3) & 1;
    int b_nh = (lane >> 4) & 1;

    const __half* gh = g_f16 + (size_t)b*HH*HH*64;

    for (int i = tid; i < 4608; i += 512)
        cpa16(smc + C1_WBASE + i*16, g_cw1 + (size_t)i*16);
    for (int i = tid; i < 2592; i += 512) {
        int pos = i >> 3, j = i & 7;
        int r = pos / 18, c = pos - r*18;
        int gy = row0 + r - 1, gx = col0 + c - 1;
        int ok = (gy >= 0 && gy < HH && gx >= 0 && gx < HH);
        const __half* src = gh + ((size_t)(ok ? gy : 0)*HH + (ok ? gx : 0))*64 + j*8;
        cpa16z(smc + (r*18 + c)*128 + (((uint32_t)j*16) ^ (((uint32_t)c&7)<<4)), src, ok ? 16 : 0);
    }
    asm volatile("cp.async.commit_group;" ::: "memory");
    if (tid < 64) sbias[tid] = bias[tid];
    asm volatile("cp.async.wait_group 0;" ::: "memory");
    __syncthreads();

    float acc[2][4][4];
    #pragma unroll
    for (int t = 0; t < 2; t++)
        #pragma unroll
        for (int u = 0; u < 4; u++)
            #pragma unroll
            for (int j = 0; j < 4; j++) acc[t][u][j] = 0.f;

    uint32_t bRowOff = (uint32_t)((nb + b_nh*8 + lr8)*128);
    uint32_t swB = (uint32_t)(lr8 << 4);

    for (int dydx = 0; dydx < 9; dydx++) {
        int dy = dydx/3, dx = dydx - dy*3;
        uint32_t wb = sb + C1_WBASE + (uint32_t)(dydx*8192) + bRowOff;
        int cA = dx + lr8 + a_mh*8;
        uint32_t swA = (uint32_t)(((dx + lr8) & 7) << 4);
        uint32_t aBase0 = sb + (uint32_t)((((wm*2 + dy)*18 + cA))*128);
        uint32_t aBase1 = aBase0 + 18*128;

        #pragma unroll
        for (int ks = 0; ks < 4; ks++) {
            uint32_t ka = (uint32_t)(((ks*2 + a_jh)*16)) ^ swA;
            uint32_t a0[4], a1[4];
            ldsm4(a0[0], a0[1], a0[2], a0[3], aBase0 + ka);
            ldsm4(a1[0], a1[1], a1[2], a1[3], aBase1 + ka);
            uint32_t kb = (uint32_t)(((ks*2 + b_jh)*16)) ^ swB;
            #pragma unroll
            for (int up = 0; up < 2; up++) {
                uint32_t br[4];
                ldsm4(br[0], br[1], br[2], br[3], wb + (uint32_t)(up*2048) + kb);
                mma16816(acc[0][2*up],   a0[0], a0[1], a0[2], a0[3], br[0], br[1]);
                mma16816(acc[0][2*up+1], a0[0], a0[1], a0[2], a0[3], br[2], br[3]);
                mma16816(acc[1][2*up],   a1[0], a1[1], a1[2], a1[3], br[0], br[1]);
                mma16816(acc[1][2*up+1], a1[0], a1[1], a1[2], a1[3], br[2], br[3]);
            }
        }
    }

    int egrp = lane >> 2, et4 = lane & 3;
    __half* outp = g_h16 + (size_t)b*HH*HH*64;
    #pragma unroll
    for (int t = 0; t < 2; t++) {
        int gy = row0 + wm*2 + t;
        #pragma unroll
        for (int u = 0; u < 4; u++) {
            int cidx = nb + u*8 + et4*2;
            float b0 = sbias[cidx], b1 = sbias[cidx+1];
            size_t o0 = ((size_t)gy*HH + col0 + egrp)*64 + cidx;
            size_t o1 = o0 + (size_t)8*64;
            *(__half2*)&outp[o0] = __floats2half2_rn(fmaxf(acc[t][u][0] + b0, 0.f),
                                                     fmaxf(acc[t][u][1] + b1, 0.f));
            *(__half2*)&outp[o1] = __floats2half2_rn(fmaxf(acc[t][u][2] + b0, 0.f),
                                                     fmaxf(acc[t][u][3] + b1, 0.f));
        }
    }
}

// ------- fused 1x1 conv -> online softmax -> stats -> (last block) ktw --------
__global__ void logits_stats(const float* __restrict__ w2, const float* __restrict__ b2,
                             const float* __restrict__ sx, const float* __restrict__ sy,
                             const float* __restrict__ op, const float* __restrict__ rh) {
    __shared__ float buf[49*196];
    __shared__ float sv[4*NGRP];
    __shared__ float b2s[NGRP];
    __shared__ float accs[196];
    __shared__ float wops[49];
    __shared__ int lastb;
    int tid = threadIdx.x;
    float* ws = buf;
    for (int i = tid; i < NGRP; i += 256) {
        sv[i] = sx[i]; sv[NGRP+i] = sy[i]; sv[2*NGRP+i] = op[i]; sv[3*NGRP+i] = rh[i];
        b2s[i] = b2[i];
    }
    for (int i = tid; i < NGRP*64; i += 256) ws[i] = w2[i];
    for (int i = tid; i < 196; i += 256) accs[i] = 0.f;
    __syncthreads();

    int t = blockIdx.x * 256 + tid;
    int b = t / (HH*HH); int pix = t % (HH*HH);
    int y = pix / HH, x = pix % HH;
    const __half2* hp = (const __half2*)(g_h16 + ((size_t)b*HH*HH + pix)*64);
    float hv[64];
    #pragma unroll
    for (int ci = 0; ci < 32; ci++) {
        float2 v = __half22float2(hp[ci]);
        hv[2*ci] = v.x; hv[2*ci+1] = v.y;
    }

    float m = -1e30f, s = 0.f, a0 = 0.f, a1 = 0.f, a2 = 0.f, a3 = 0.f;
    for (int g = 0; g < NGRP; g++) {
        float l = b2s[g];
        const float* wg = ws + g*64;
        #pragma unroll
        for (int ci = 0; ci < 64; ci += 4) {
            float4 wv = *(const float4*)(wg + ci);
            l += hv[ci]*wv.x + hv[ci+1]*wv.y + hv[ci+2]*wv.z + hv[ci+3]*wv.w;
        }
        float mn = fmaxf(m, l);
        float sc = __expf(m - mn);
        float e  = __expf(l - mn);
        s  = s*sc + e;
        a0 = a0*sc + e*sv[g];
        a1 = a1*sc + e*sv[NGRP+g];
        a2 = a2*sc + e*sv[2*NGRP+g];
        a3 = a3*sc + e*sv[3*NGRP+g];
        m = mn;
    }
    float inv = 1.f / s;
    int p = (y % 7)*7 + (x % 7);
    atomicAdd(&accs[p*4+0], a0*inv);
    atomicAdd(&accs[p*4+1], a1*inv);
    atomicAdd(&accs[p*4+2], a2*inv);
    atomicAdd(&accs[p*4+3], a3*inv);
    __syncthreads();
    for (int i = tid; i < 196; i += 256) atomicAdd(&g_wstat[i], accs[i]);

    __threadfence();
    if (tid == 0) lastb = (atomicAdd(&g_ctr, 1) == (int)gridDim.x - 1);
    __syncthreads();
    if (!lastb) return;
    if (tid == 0) g_ctr = 0;

    float* kpad = buf;
    for (int i = tid; i < 49*196; i += 256) kpad[i] = 0.f;
    __syncthreads();
    if (tid < 49) {
        int p2 = tid;
        const float inv1024 = 1.f/1024.f;
        float wsx = g_wstat[p2*4+0]*inv1024;
        float wsy = g_wstat[p2*4+1]*inv1024;
        float wop = g_wstat[p2*4+2]*inv1024;
        float wr  = g_wstat[p2*4+3]*inv1024;
        wops[p2] = wop;
        float c00 = wsx*wsx + 1e-5f;
        float c11 = wsy*wsy + 1e-5f;
        float c01 = wr*wsx*wsy;
        float det = c00*c11 - c01*c01;
        float i00 = c11/det, i11 = c00/det, i01 = -c01/det;
        float norm = 1.f/(2.f*3.14159265358979f*sqrtf(det));
        float kv[25]; float kmx = 0.f;
        #pragma unroll
        for (int i = 0; i < 5; i++)
            #pragma unroll
            for (int j = 0; j < 5; j++) {
                float yv = -5.f + 2.5f*i;
                float xv = -5.f + 2.5f*j;
                float z = -0.5f*(i00*xv*xv + 2.f*i01*xv*yv + i11*yv*yv);
                float k = expf(z)*norm;
                kv[i*5+j] = k; kmx = fmaxf(kmx, k);
            }
        float im = 1.f/kmx;
        #pragma unroll
        for (int i = 0; i < 5; i++)
            #pragma unroll
            for (int j = 0; j < 5; j++)
                kpad[p2*196 + (i+4)*14 + (j+4)] = kv[i*5+j]*im;
    }
    __syncthreads();
    for (int idx = tid; idx < 49*196; idx += 256) {
        int p2 = idx/196, hw = idx%196, h = hw/14, w = hw%14;
        float txo = (0.5f - (float)(p2/7)*(1.f/7.f))*2.f;
        float tyo = (0.5f - (float)(p2%7)*(1.f/7.f))*2.f;
        float gxv = -1.f + (2.f/13.f)*w + txo;
        float gyv = -1.f + (2.f/13.f)*h + tyo;
        float px = (gxv + 1.f)*0.5f*13.f;
        float py = (gyv + 1.f)*0.5f*13.f;
        float x0f = floorf(px), y0f = floorf(py);
        int x0 = (int)x0f, y0 = (int)y0f;
        float wx = px - x0f, wy = py - y0f;
        float s00 = (y0   >= 0 && y0   < 14 && x0   >= 0 && x0   < 14) ? kpad[p2*196 + y0*14 + x0]       : 0.f;
        float s01 = (y0   >= 0 && y0   < 14 && x0+1 >= 0 && x0+1 < 14) ? kpad[p2*196 + y0*14 + x0+1]     : 0.f;
        float s10 = (y0+1 >= 0 && y0+1 < 14 && x0   >= 0 && x0   < 14) ? kpad[p2*196 + (y0+1)*14 + x0]   : 0.f;
        float s11 = (y0+1 >= 0 && y0+1 < 14 && x0+1 >= 0 && x0+1 < 14) ? kpad[p2*196 + (y0+1)*14 + x0+1] : 0.f;
        float kt = s00*(1.f-wy)*(1.f-wx) + s01*(1.f-wy)*wx + s10*wy*(1.f-wx) + s11*wy*wx;
        g_ktw[idx] = kt * wops[p2];
    }
}

// ------- splat -> NHWC fp16 (392 thr, half/thread) + pack conv224 weights -----
#define SPLAT_SMEM ((49*196 + 49*64)*4)
__global__ void splat(const float* __restrict__ feat,
                      const float* __restrict__ wc, const float* __restrict__ wf) {
    extern __shared__ float sm[];
    float* kts = sm;
    float* fp  = sm + 49*196;
    int bl = blockIdx.x;
    int b = bl / 256; int l = bl % 256; int pr = l / 16, pc = l % 16;
    int tid = threadIdx.x;   // 392

    for (int i = bl*392 + tid; i < 294912; i += 1024*392) {
        int ci = i & 63; int t = i >> 6;
        int co = t & 127; t >>= 7;
        int dydx = t % 9; t /= 9;
        int half = t & 1; int sel = t >> 1;
        const float* W = sel ? wf : wc;
        float v = W[(size_t)(half*128 + co)*576 + ci*9 + dydx];
        size_t base = ((size_t)((sel*2 + half)*9 + dydx))*16384;
        uint32_t off = (uint32_t)co*128 + (((uint32_t)(ci>>3)*16) ^ (((uint32_t)co&7)<<4)) + (ci&7)*2;
        *(__half*)(g_cw + base + off) = __float2half(v);
    }

    for (int i = tid; i < 49*196; i += 392) kts[i] = g_ktw[i];
    const float* fb = feat + (size_t)b*64*HH*HH;
    for (int i = tid; i < 49*64; i += 392) {
        int p = i >> 6, c = i & 63;
        fp[i] = fb[((size_t)c*HH + pr*7 + p/7)*HH + pc*7 + p%7];
    }
    __syncthreads();
    int half = tid / 196;
    int pix  = tid % 196;
    int h = pix/14, w = pix%14;
    int oy = pr*14 + h, ox = pc*14 + w;
    size_t pixb = ((size_t)b*H2 + oy)*H2 + ox;
    __half* gh = g_gfh + pixb*64 + half*32;
    float a[32];
    #pragma unroll
    for (int j = 0; j < 32; j++) a[j] = 0.f;
    for (int p = 0; p < 49; p++) {
        float k = kts[p*196 + pix];
        const float4* f4 = (const float4*)(fp + p*64 + half*32);
        #pragma unroll
        for (int j = 0; j < 8; j++) {
            float4 v = f4[j];
            a[j*4+0] += k*v.x; a[j*4+1] += k*v.y;
            a[j*4+2] += k*v.z; a[j*4+3] += k*v.w;
        }
    }
    #pragma unroll
    for (int j = 0; j < 32; j += 4) {
        *(__half2*)(gh + j)     = __floats2half2_rn(__saturatef(a[j]),   __saturatef(a[j+1]));
        *(__half2*)(gh + j + 2) = __floats2half2_rn(__saturatef(a[j+2]), __saturatef(a[j+3]));
    }
}

// ------- conv3x3 64->256 @224 via mma.sync (all weights resident) -------------
#define CM_WBASE 41472
#define CM_SMEM  (41472 + 9*16384)   // 188928

__global__ void __launch_bounds__(512, 1) conv224m(const float* __restrict__ bias_c,
                                                   const float* __restrict__ bias_f) {
    extern __shared__ __align__(16) char smc[];
    __shared__ float sbias[128];
    uint32_t sb;
    asm("{ .reg .u64 t; cvta.to.shared.u64 t, %1; cvt.u32.u64 %0, t; }" : "=r"(sb) : "l"(smc));
    int tid = threadIdx.x, wid = tid >> 5, lane = tid & 31;
    int bt = blockIdx.x, cohalf = blockIdx.y;
    int sel = blockIdx.z & 1, b = blockIdx.z >> 1;
    int row0 = (bt/14)*16, col0 = (bt%14)*16;
    int wm = wid >> 1, wn = wid & 1;
    int nb = wn*64;

    int lr8  = lane & 7;
    int a_mh = (lane >> 3) & 1;
    int a_jh = (lane >> 4) & 1;
    int b_jh = (lane >> 3) & 1;
    int b_nh = (lane >> 4) & 1;

    const __half* gh = g_gfh + (size_t)b*H2*H2*64;
    const unsigned char* wsrc = g_cw + (size_t)(sel*2 + cohalf)*9*16384;
    const float* bias = sel ? bias_f : bias_c;

    // all 9 weight taps + A halo, one prologue
    for (int i = tid; i < 9216; i += 512)
        cpa16(smc + CM_WBASE + i*16, wsrc + (size_t)i*16);
    for (int i = tid; i < 2592; i += 512) {
        int pos = i >> 3, j = i & 7;
        int r = pos / 18, c = pos - r*18;
        int gy = row0 + r - 1, gx = col0 + c - 1;
        int ok = (gy >= 0 && gy < H2 && gx >= 0 && gx < H2);
        const __half* src = gh + ((size_t)(ok ? gy : 0)*H2 + (ok ? gx : 0))*64 + j*8;
        cpa16z(smc + (r*18 + c)*128 + (((uint32_t)j*16) ^ (((uint32_t)c&7)<<4)), src, ok ? 16 : 0);
    }
    asm volatile("cp.async.commit_group;" ::: "memory");
    if (tid < 128) sbias[tid] = bias[cohalf*128 + tid];
    asm volatile("cp.async.wait_group 0;" ::: "memory");
    __syncthreads();

    float acc[2][8][4];
    #pragma unroll
    for (int t = 0; t < 2; t++)
        #pragma unroll
        for (int u = 0; u < 8; u++)
            #pragma unroll
            for (int j = 0; j < 4; j++) acc[t][u][j] = 0.f;

    uint32_t bRowOff = (uint32_t)((nb + b_nh*8 + lr8)*128);
    uint32_t swB = (uint32_t)(lr8 << 4);

    for (int dydx = 0; dydx < 9; dydx++) {
        int dy = dydx/3, dx = dydx - dy*3;
        uint32_t wb = sb + CM_WBASE + (uint32_t)(dydx*16384) + bRowOff;
        int cA = dx + lr8 + a_mh*8;
        uint32_t swA = (uint32_t)(((dx + lr8) & 7) << 4);
        uint32_t aBase0 = sb + (uint32_t)((((wm*2 + dy)*18 + cA))*128);
        uint32_t aBase1 = aBase0 + 18*128;

        #pragma unroll
        for (int ks = 0; ks < 4; ks++) {
            uint32_t ka = (uint32_t)(((ks*2 + a_jh)*16)) ^ swA;
            uint32_t a0[4], a1[4];
            ldsm4(a0[0], a0[1], a0[2], a0[3], aBase0 + ka);
            ldsm4(a1[0], a1[1], a1[2], a1[3], aBase1 + ka);
            uint32_t kb = (uint32_t)(((ks*2 + b_jh)*16)) ^ swB;
            #pragma unroll
            for (int up = 0; up < 4; up++) {
                uint32_t br[4];
                ldsm4(br[0], br[1], br[2], br[3], wb + (uint32_t)(up*2048) + kb);
                mma16816(acc[0][2*up],   a0[0], a0[1], a0[2], a0[3], br[0], br[1]);
                mma16816(acc[0][2*up+1], a0[0], a0[1], a0[2], a0[3], br[2], br[3]);
                mma16816(acc[1][2*up],   a1[0], a1[1], a1[2], a1[3], br[0], br[1]);
                mma16816(acc[1][2*up+1], a1[0], a1[1], a1[2], a1[3], br[2], br[3]);
            }
        }
    }

    int egrp = lane >> 2, et4 = lane & 3;
    __half* outp = sel ? g_freqh : g_coefh;
    #pragma unroll
    for (int t = 0; t < 2; t++) {
        int gy = row0 + wm*2 + t;
        #pragma unroll
        for (int u = 0; u < 8; u++) {
            int cidx = nb + u*8 + et4*2;
            float b0 = sbias[cidx], b1 = sbias[cidx+1];
            size_t o0 = (((size_t)b*H2 + gy)*H2 + col0 + egrp)*256 + cohalf*128 + cidx;
            size_t o1 = o0 + (size_t)8*256;
            *(__half2*)&outp[o0] = __floats2half2_rn(acc[t][u][0] + b0, acc[t][u][1] + b1);
            *(__half2*)&outp[o1] = __floats2half2_rn(acc[t][u][2] + b0, acc[t][u][3] + b1);
        }
    }
}

// ---------------- gather + fourier basis -> X0 fp16 (+ zero out) --------------
__global__ void gather_basis(const float* __restrict__ coord,
                             const float* __restrict__ cell,
                             const float* __restrict__ phase_w,
                             float* __restrict__ outz) {
    int gid = blockIdx.x*256 + threadIdx.x;
    if (gid < MTOT*3) outz[gid] = 0.f;
    int warp = threadIdx.x / 32, lane = threadIdx.x % 32;
    int m = blockIdx.x * 8 + warp;
    int b = m / QQ; int q = m % QQ;
    float cy = coord[((size_t)b*QQ + q)*2 + 0];
    float cx = coord[((size_t)b*QQ + q)*2 + 1];
    int ix = (int)rintf(((cx + 1.f)*(float)H2 - 1.f)*0.5f);
    int iy = (int)rintf(((cy + 1.f)*(float)H2 - 1.f)*0.5f);
    bool ok = (ix >= 0 && ix < H2 && iy >= 0 && iy < H2);
    __half* xh = g_X0h + (size_t)m*HID;
    if (!ok) {
        __half z = __float2half(0.f);
        #pragma unroll
        for (int kk = 0; kk < 4; kk++) {
            int k = lane + kk*32;
            xh[k] = z; xh[128+k] = z;
        }
        return;
    }
    float fcy = -1.f + 1.f/(float)H2 + (2.f/(float)H2)*(float)iy;
    float fcx = -1.f + 1.f/(float)H2 + (2.f/(float)H2)*(float)ix;
    float rely = (cy - fcy)*(float)H2;
    float relx = (cx - fcx)*(float)H2;
    float rc0 = cell[((size_t)b*QQ + q)*2 + 0]*(float)H2;
    float rc1 = cell[((size_t)b*QQ + q)*2 + 1]*(float)H2;
    size_t base = (((size_t)b*H2 + iy)*H2 + ix)*HID;
    const __half*  cf = g_coefh + base;
    const __half2* fq = (const __half2*)(g_freqh + base);
    const float2* pw = (const float2*)phase_w;
    const float PI = 3.14159265358979f;
    #pragma unroll
    for (int kk = 0; kk < 4; kk++) {
        int k = lane + kk*32;
        float2 f = __half22float2(fq[k]);
        float2 p = pw[k];
        float s = (f.x*rely + f.y*relx + rc0*p.x + rc1*p.y) * PI;
        xh[k]     = __float2half(__half2float(cf[k])       * __cosf(s));
        xh[128+k] = __float2half(__half2float(cf[128 + k]) * __sinf(s));
    }
}

// ---------------- mma.sync fp16 GEMM (1-pass + ldmatrix) ----------------------
#define GM_BB 0
#define GM_AB 65536
#define GM_SMEM (65536 + 2*16384)

__global__ void __launch_bounds__(256, 1) gemm_mma(const float* __restrict__ bias, int layer,
                                                   const float* __restrict__ w3,
                                                   const float* __restrict__ b3,
                                                   float* __restrict__ out) {
    extern __shared__ __align__(16) char smc[];
    __shared__ float sbias[128];
    __shared__ float w3s[3*128];
    uint32_t sb;
    asm("{ .reg .u64 t; cvta.to.shared.u64 t, %1; cvt.u32.u64 %0, t; }" : "=r"(sb) : "l"(smc));
    int tid = threadIdx.x, wid = tid >> 5, lane = tid & 31;
    int m0 = blockIdx.x * 128;
    int n0 = blockIdx.y * 128;
    int wm = wid >> 1, wn = wid & 1;
    int mb = wm * 32, nb = wn * 64;

    int lr8  = lane & 7;
    int a_mh = (lane >> 3) & 1;
    int a_jh = (lane >> 4) & 1;
    int b_jh = (lane >> 3) & 1;
    int b_nh = (lane >> 4) & 1;

    const __half* Ah = layer ? g_X1h : g_X0h;
    const __half* Wh = g_Wh[layer];

    for (int i = tid; i < 4096; i += 256) {
        int n = i >> 5; int j = i & 31;
        const __half* src = Wh + (size_t)(n0 + n)*256 + j*8;
        cpa16(smc + GM_BB + n*512 + ((j*16) ^ ((n&7)<<4)), src);
    }
    for (int i = tid; i < 1024; i += 256) {
        int m = i >> 3; int j = i & 7;
        const __half* src = Ah + (size_t)(m0 + m)*256 + j*8;
        cpa16(smc + GM_AB + m*128 + ((j*16) ^ ((m&7)<<4)), src);
    }
    asm volatile("cp.async.commit_group;" ::: "memory");
    if (tid < 128) {
        sbias[tid] = bias[n0 + tid];
        if (layer) {
            w3s[tid]       = w3[0*256 + n0 + tid];
            w3s[128 + tid] = w3[1*256 + n0 + tid];
            w3s[256 + tid] = w3[2*256 + n0 + tid];
        }
    }

    float acc[2][8][4];
    #pragma unroll
    for (int t = 0; t < 2; t++)
        #pragma unroll
        for (int u = 0; u < 8; u++)
            #pragma unroll
            for (int j = 0; j < 4; j++) acc[t][u][j] = 0.f;

    uint32_t aRowOff = (uint32_t)((a_mh*8 + lr8)*128);
    uint32_t swA = (uint32_t)(lr8 << 4);
    uint32_t bRowOff = (uint32_t)((nb + b_nh*8 + lr8)*512);
    uint32_t swB = swA;
    uint32_t bB = sb + GM_BB + bRowOff;

    for (int c = 0; c < 4; c++) {
        if (c < 3) {
            int cn = c + 1;
            char* dstb = smc + GM_AB + (cn & 1)*16384;
            for (int i = tid; i < 1024; i += 256) {
                int m = i >> 3; int j = i & 7;
                const __half* src = Ah + (size_t)(m0 + m)*256 + cn*64 + j*8;
                cpa16(dstb + m*128 + ((j*16) ^ ((m&7)<<4)), src);
            }
            asm volatile("cp.async.commit_group;" ::: "memory");
            asm volatile("cp.async.wait_group 1;" ::: "memory");
        } else {
            asm volatile("cp.async.wait_group 0;" ::: "memory");
        }
        __syncthreads();

        uint32_t bA = sb + GM_AB + (c & 1)*16384 + aRowOff;
        #pragma unroll
        for (int ks = 0; ks < 4; ks++) {
            uint32_t ka = (uint32_t)(((ks*2 + a_jh)*16)) ^ swA;
            uint32_t a0[4], a1[4];
            ldsm4(a0[0], a0[1], a0[2], a0[3], bA + (uint32_t)(mb*128) + ka);
            ldsm4(a1[0], a1[1], a1[2], a1[3], bA + (uint32_t)((mb+16)*128) + ka);
            uint32_t kb = (uint32_t)(((c*8 + ks*2 + b_jh)*16)) ^ swB;
            #pragma unroll
            for (int up = 0; up < 4; up++) {
                uint32_t br[4];
                ldsm4(br[0], br[1], br[2], br[3], bB + (uint32_t)(up*8192) + kb);
                mma16816(acc[0][2*up],   a0[0], a0[1], a0[2], a0[3], br[0], br[1]);
                mma16816(acc[0][2*up+1], a0[0], a0[1], a0[2], a0[3], br[2], br[3]);
                mma16816(acc[1][2*up],   a1[0], a1[1], a1[2], a1[3], br[0], br[1]);
                mma16816(acc[1][2*up+1], a1[0], a1[1], a1[2], a1[3], br[2], br[3]);
            }
        }
        __syncthreads();
    }

    int grp = lane >> 2, t4 = lane & 3;
    if (layer == 0) {
        #pragma unroll
        for (int t = 0; t < 2; t++) {
            int r0 = m0 + mb + t*16 + grp;
            int r1 = r0 + 8;
            #pragma unroll
            for (int u = 0; u < 8; u++) {
                int cb = nb + u*8 + t4*2;
                float b0v = sbias[cb], b1v = sbias[cb+1];
                float v00 = fmaxf(acc[t][u][0] + b0v, 0.f);
                float v01 = fmaxf(acc[t][u][1] + b1v, 0.f);
                float v10 = fmaxf(acc[t][u][2] + b0v, 0.f);
                float v11 = fmaxf(acc[t][u][3] + b1v, 0.f);
                int gcol = n0 + cb;
                *(__half2*)&g_X1h[(size_t)r0*256 + gcol] = __floats2half2_rn(v00, v01);
                *(__half2*)&g_X1h[(size_t)r1*256 + gcol] = __floats2half2_rn(v10, v11);
            }
        }
    } else {
        #pragma unroll
        for (int t = 0; t < 2; t++) {
            int r0 = m0 + mb + t*16 + grp;
            int r1 = r0 + 8;
            float p0[3] = {0.f, 0.f, 0.f};
            float p1[3] = {0.f, 0.f, 0.f};
            #pragma unroll
            for (int u = 0; u < 8; u++) {
                int cb = nb + u*8 + t4*2;
                float b0v = sbias[cb], b1v = sbias[cb+1];
                float v00 = fmaxf(acc[t][u][0] + b0v, 0.f);
                float v01 = fmaxf(acc[t][u][1] + b1v, 0.f);
                float v10 = fmaxf(acc[t][u][2] + b0v, 0.f);
                float v11 = fmaxf(acc[t][u][3] + b1v, 0.f);
                #pragma unroll
                for (int cc = 0; cc < 3; cc++) {
                    float w0 = w3s[cc*128 + cb], w1 = w3s[cc*128 + cb + 1];
                    p0[cc] += v00*w0 + v01*w1;
                    p1[cc] += v10*w0 + v11*w1;
                }
            }
            #pragma unroll
            for (int cc = 0; cc < 3; cc++) {
                p0[cc] += __shfl_xor_sync(0xffffffffu, p0[cc], 1);
                p0[cc] += __shfl_xor_sync(0xffffffffu, p0[cc], 2);
                p1[cc] += __shfl_xor_sync(0xffffffffu, p1[cc], 1);
                p1[cc] += __shfl_xor_sync(0xffffffffu, p1[cc], 2);
            }
            if (t4 == 0) {
                #pragma unroll
                for (int cc = 0; cc < 3; cc++) {
                    float bb = (n0 == 0) ? b3[cc] : 0.f;
                    atomicAdd(&out[(size_t)r0*3 + cc], p0[cc] + bb);
                    atomicAdd(&out[(size_t)r1*3 + cc], p1[cc] + bb);
                }
            }
        }
    }
}

// ---------------- launch -------------------------------------------------------
extern "C" void kernel_launch(void* const* d_in, const int* in_sizes, int n_in,
                              void* d_out, int out_size) {
    const float* feat    = (const float*)d_in[0];
    const float* coord   = (const float*)d_in[1];
    const float* cell    = (const float*)d_in[2];
    const float* cls_w1  = (const float*)d_in[3];
    const float* cls_b1  = (const float*)d_in[4];
    const float* cls_w2  = (const float*)d_in[5];
    const float* cls_b2  = (const float*)d_in[6];
    const float* sigma_x = (const float*)d_in[7];
    const float* sigma_y = (const float*)d_in[8];
    const float* opacity = (const float*)d_in[9];
    const float* rho     = (const float*)d_in[10];
    const float* coef_w  = (const float*)d_in[11];
    const float* coef_b  = (const float*)d_in[12];
    const float* freq_w  = (const float*)d_in[13];
    const float* freq_b  = (const float*)d_in[14];
    const float* phase_w = (const float*)d_in[15];
    const float* mlp_w1  = (const float*)d_in[16];
    const float* mlp_b1  = (const float*)d_in[17];
    const float* mlp_w2  = (const float*)d_in[18];
    const float* mlp_b2  = (const float*)d_in[19];
    const float* mlp_w3  = (const float*)d_in[20];
    const float* mlp_b3  = (const float*)d_in[21];
    float* out = (float*)d_out;

    cudaFuncSetAttribute(conv112t, cudaFuncAttributeMaxDynamicSharedMemorySize, C1_SMEM);
    cudaFuncSetAttribute(splat,    cudaFuncAttributeMaxDynamicSharedMemorySize, SPLAT_SMEM);
    cudaFuncSetAttribute(conv224m, cudaFuncAttributeMaxDynamicSharedMemorySize, CM_SMEM);
    cudaFuncSetAttribute(gemm_mma, cudaFuncAttributeMaxDynamicSharedMemorySize, GM_SMEM);

    feat_prep<<<12544, 256>>>(feat, cls_w1, mlp_w1, mlp_w2);                       // #1
    conv112t<<<dim3(49, 1, BB), 512, C1_SMEM>>>(cls_b1);                           // #2
    logits_stats<<<196, 256>>>(cls_w2, cls_b2, sigma_x, sigma_y, opacity, rho);    // #3
    splat<<<1024, 392, SPLAT_SMEM>>>(feat, coef_w, freq_w);                        // #4
    conv224m<<<dim3(196, 2, BB*2), 512, CM_SMEM>>>(coef_b, freq_b);                // #5
    gather_basis<<<MTOT/8, 256>>>(coord, cell, phase_w, out);                      // #6
    gemm_mma<<<dim3(MTOT/128, 2), 256, GM_SMEM>>>(mlp_b1, 0, mlp_w3, mlp_b3, out); // #7
    gemm_mma<<<dim3(MTOT/128, 2), 256, GM_SMEM>>>(mlp_b2, 1, mlp_w3, mlp_b3, out); // #8
}

// round 17
// speedup vs baseline: 1.4115x; 1.4115x over previous
#include <cuda_runtime.h>
#include <cuda_fp16.h>
#include <math.h>
#include <stdint.h>

#define CIN 64
#define NGRP 100
#define HID 256
#define BB 4
#define HH 112
#define H2 224
#define QQ 50176
#define MTOT (BB*QQ)   // 200704

typedef unsigned long long ull;

__device__ __forceinline__ void cpa16(void* dst, const void* src) {
    unsigned d = (unsigned)__cvta_generic_to_shared(dst);
    asm volatile("cp.async.cg.shared.global [%0], [%1], 16;" :: "r"(d), "l"(src));
}
__device__ __forceinline__ void cpa16z(void* dst, const void* src, int sz) {
    unsigned d = (unsigned)__cvta_generic_to_shared(dst);
    asm volatile("cp.async.cg.shared.global [%0], [%1], 16, %2;" :: "r"(d), "l"(src), "r"(sz));
}
__device__ __forceinline__ void ldsm4(uint32_t& r0, uint32_t& r1, uint32_t& r2, uint32_t& r3, uint32_t a) {
    asm volatile("ldmatrix.sync.aligned.m8n8.x4.shared.b16 {%0,%1,%2,%3}, [%4];"
        : "=r"(r0), "=r"(r1), "=r"(r2), "=r"(r3) : "r"(a));
}
__device__ __forceinline__ void mma16816(float* c, uint32_t a0, uint32_t a1, uint32_t a2, uint32_t a3,
                                         uint32_t b0, uint32_t b1) {
    asm volatile("mma.sync.aligned.m16n8k16.row.col.f32.f16.f16.f32 "
        "{%0,%1,%2,%3},{%4,%5,%6,%7},{%8,%9},{%0,%1,%2,%3};"
        : "+f"(c[0]), "+f"(c[1]), "+f"(c[2]), "+f"(c[3])
        : "r"(a0), "r"(a1), "r"(a2), "r"(a3), "r"(b0), "r"(b1));
}

// ---------------- scratch -----------------------------------------------------
__device__ __align__(16) __half g_f16[(size_t)BB*HH*HH*64];   // feat NHWC fp16
__device__ __align__(16) __half g_h16[(size_t)BB*HH*HH*64];   // conv112 out NHWC fp16
__device__ float g_wstat[49*4];
__device__ int   g_ctr;
__device__ float g_ktw[49*196];
__device__ __align__(16) __half g_gfh[(size_t)BB*H2*H2*64];    // gfeat NHWC fp16
__device__ __align__(16) __half g_coefh[(size_t)BB*H2*H2*HID]; // coef fp16
__device__ __align__(16) __half g_freqh[(size_t)BB*H2*H2*HID]; // freq fp16
__device__ __align__(16) __half g_X0h[(size_t)MTOT*HID];
__device__ __align__(16) __half g_X1h[(size_t)MTOT*HID];
__device__ __align__(16) unsigned char g_cw[(size_t)2*2*9*16384];  // conv224 weights
__device__ __align__(16) unsigned char g_cw1[(size_t)9*8192];      // conv112 weights
__device__ __align__(16) __half g_Wh[2][65536];

// ------- prep: feat NCHW->NHWC fp16, pack conv112 + MLP weights, zero stats ---
__global__ void feat_prep(const float* __restrict__ feat,
                          const float* __restrict__ cls_w1,
                          const float* __restrict__ w1, const float* __restrict__ w2) {
    int gid = blockIdx.x*256 + threadIdx.x;
    if (blockIdx.x == 0 && threadIdx.x < 196) g_wstat[threadIdx.x] = 0.f;
    if (gid < BB*HH*HH*64) {
        int c = gid & 63; int e = gid >> 6;
        int x = e % HH; e /= HH; int y = e % HH; int b = e / HH;
        g_f16[gid] = __float2half(feat[(((size_t)b*64 + c)*HH + y)*HH + x]);
    }
    if (gid < 36864) {
        int ci = gid & 63; int t = gid >> 6;
        int co = t & 63; int tap = t >> 6;
        float v = cls_w1[(size_t)co*576 + ci*9 + tap];
        uint32_t off = (uint32_t)co*128 + (((uint32_t)(ci>>3)*16) ^ (((uint32_t)co&7)<<4)) + (ci&7)*2;
        *(__half*)(g_cw1 + (size_t)tap*8192 + off) = __float2half(v);
    }
    if (gid < 131072) {
        int l = gid >> 16; int e = gid & 65535;
        const float* W = l ? w2 : w1;
        g_Wh[l][e] = __float2half(W[e]);
    }
}

// ---------------- conv3x3 64->64 @112 via mma.sync (fp16, 2-buf pipeline) -----
#define C1_WBASE 41472
#define C1_WBUF  8192
#define C1_SMEM  (41472 + 2*8192)

__global__ void __launch_bounds__(512, 1) conv112t(const float* __restrict__ bias) {
    extern __shared__ __align__(16) char smc[];
    __shared__ float sbias[64];
    uint32_t sb;
    asm("{ .reg .u64 t; cvta.to.shared.u64 t, %1; cvt.u32.u64 %0, t; }" : "=r"(sb) : "l"(smc));
    int tid = threadIdx.x, wid = tid >> 5, lane = tid & 31;
    int bt = blockIdx.x, b = blockIdx.z;
    int row0 = (bt/7)*16, col0 = (bt%7)*16;
    int wm = wid >> 1, wn = wid & 1;
    int nb = wn*32;

    int lr8  = lane & 7;
    int a_mh = (lane >> 3) & 1;
    int a_jh = (lane >> 4) & 1;
    int b_jh = (lane >> 3) & 1;
    int b_nh = (lane >> 4) & 1;

    const __half* gh = g_f16 + (size_t)b*HH*HH*64;

    for (int i = tid; i < 512; i += 512)
        cpa16(smc + C1_WBASE + i*16, g_cw1 + i*16);
    for (int i = tid; i < 2592; i += 512) {
        int pos = i >> 3, j = i & 7;
        int r = pos / 18, c = pos - r*18;
        int gy = row0 + r - 1, gx = col0 + c - 1;
        int ok = (gy >= 0 && gy < HH && gx >= 0 && gx < HH);
        const __half* src = gh + ((size_t)(ok ? gy : 0)*HH + (ok ? gx : 0))*64 + j*8;
        cpa16z(smc + (r*18 + c)*128 + (((uint32_t)j*16) ^ (((uint32_t)c&7)<<4)), src, ok ? 16 : 0);
    }
    asm volatile("cp.async.commit_group;" ::: "memory");
    if (tid < 64) sbias[tid] = bias[tid];

    float acc[2][4][4];
    #pragma unroll
    for (int t = 0; t < 2; t++)
        #pragma unroll
        for (int u = 0; u < 4; u++)
            #pragma unroll
            for (int j = 0; j < 4; j++) acc[t][u][j] = 0.f;

    uint32_t bRowOff = (uint32_t)((nb + b_nh*8 + lr8)*128);
    uint32_t swB = (uint32_t)(lr8 << 4);

    for (int dydx = 0; dydx < 9; dydx++) {
        if (dydx < 8) {
            const unsigned char* src = g_cw1 + (size_t)(dydx+1)*8192;
            char* dst = smc + C1_WBASE + ((dydx+1)&1)*C1_WBUF;
            for (int i = tid; i < 512; i += 512)
                cpa16(dst + i*16, src + i*16);
            asm volatile("cp.async.commit_group;" ::: "memory");
            asm volatile("cp.async.wait_group 1;" ::: "memory");
        } else {
            asm volatile("cp.async.wait_group 0;" ::: "memory");
        }
        __syncthreads();

        int dy = dydx/3, dx = dydx - dy*3;
        uint32_t wb = sb + C1_WBASE + (uint32_t)((dydx&1)*C1_WBUF) + bRowOff;

        int cA = dx + lr8 + a_mh*8;
        uint32_t swA = (uint32_t)(((dx + lr8) & 7) << 4);
        uint32_t aBase0 = sb + (uint32_t)((((wm*2 + dy)*18 + cA))*128);
        uint32_t aBase1 = aBase0 + 18*128;

        #pragma unroll
        for (int ks = 0; ks < 4; ks++) {
            uint32_t ka = (uint32_t)(((ks*2 + a_jh)*16)) ^ swA;
            uint32_t a0[4], a1[4];
            ldsm4(a0[0], a0[1], a0[2], a0[3], aBase0 + ka);
            ldsm4(a1[0], a1[1], a1[2], a1[3], aBase1 + ka);
            uint32_t kb = (uint32_t)(((ks*2 + b_jh)*16)) ^ swB;
            #pragma unroll
            for (int up = 0; up < 2; up++) {
                uint32_t br[4];
                ldsm4(br[0], br[1], br[2], br[3], wb + (uint32_t)(up*2048) + kb);
                mma16816(acc[0][2*up],   a0[0], a0[1], a0[2], a0[3], br[0], br[1]);
                mma16816(acc[0][2*up+1], a0[0], a0[1], a0[2], a0[3], br[2], br[3]);
                mma16816(acc[1][2*up],   a1[0], a1[1], a1[2], a1[3], br[0], br[1]);
                mma16816(acc[1][2*up+1], a1[0], a1[1], a1[2], a1[3], br[2], br[3]);
            }
        }
        __syncthreads();
    }

    int egrp = lane >> 2, et4 = lane & 3;
    __half* outp = g_h16 + (size_t)b*HH*HH*64;
    #pragma unroll
    for (int t = 0; t < 2; t++) {
        int gy = row0 + wm*2 + t;
        #pragma unroll
        for (int u = 0; u < 4; u++) {
            int cidx = nb + u*8 + et4*2;
            float b0 = sbias[cidx], b1 = sbias[cidx+1];
            size_t o0 = ((size_t)gy*HH + col0 + egrp)*64 + cidx;
            size_t o1 = o0 + (size_t)8*64;
            *(__half2*)&outp[o0] = __floats2half2_rn(fmaxf(acc[t][u][0] + b0, 0.f),
                                                     fmaxf(acc[t][u][1] + b1, 0.f));
            *(__half2*)&outp[o1] = __floats2half2_rn(fmaxf(acc[t][u][2] + b0, 0.f),
                                                     fmaxf(acc[t][u][3] + b1, 0.f));
        }
    }
}

// ------- fused 1x1 conv -> online softmax -> stats -> (last block) ktw --------
__global__ void logits_stats(const float* __restrict__ w2, const float* __restrict__ b2,
                             const float* __restrict__ sx, const float* __restrict__ sy,
                             const float* __restrict__ op, const float* __restrict__ rh) {
    __shared__ float buf[49*196];
    __shared__ float sv[4*NGRP];
    __shared__ float b2s[NGRP];
    __shared__ float accs[196];
    __shared__ float wops[49];
    __shared__ int lastb;
    int tid = threadIdx.x;
    float* ws = buf;
    for (int i = tid; i < NGRP; i += 256) {
        sv[i] = sx[i]; sv[NGRP+i] = sy[i]; sv[2*NGRP+i] = op[i]; sv[3*NGRP+i] = rh[i];
        b2s[i] = b2[i];
    }
    for (int i = tid; i < NGRP*64; i += 256) ws[i] = w2[i];
    for (int i = tid; i < 196; i += 256) accs[i] = 0.f;
    __syncthreads();

    int t = blockIdx.x * 256 + tid;
    int b = t / (HH*HH); int pix = t % (HH*HH);
    int y = pix / HH, x = pix % HH;
    const __half2* hp = (const __half2*)(g_h16 + ((size_t)b*HH*HH + pix)*64);
    float hv[64];
    #pragma unroll
    for (int ci = 0; ci < 32; ci++) {
        float2 v = __half22float2(hp[ci]);
        hv[2*ci] = v.x; hv[2*ci+1] = v.y;
    }

    float m = -1e30f, s = 0.f, a0 = 0.f, a1 = 0.f, a2 = 0.f, a3 = 0.f;
    for (int g = 0; g < NGRP; g++) {
        float l = b2s[g];
        const float* wg = ws + g*64;
        #pragma unroll
        for (int ci = 0; ci < 64; ci += 4) {
            float4 wv = *(const float4*)(wg + ci);
            l += hv[ci]*wv.x + hv[ci+1]*wv.y + hv[ci+2]*wv.z + hv[ci+3]*wv.w;
        }
        float mn = fmaxf(m, l);
        float sc = __expf(m - mn);
        float e  = __expf(l - mn);
        s  = s*sc + e;
        a0 = a0*sc + e*sv[g];
        a1 = a1*sc + e*sv[NGRP+g];
        a2 = a2*sc + e*sv[2*NGRP+g];
        a3 = a3*sc + e*sv[3*NGRP+g];
        m = mn;
    }
    float inv = 1.f / s;
    int p = (y % 7)*7 + (x % 7);
    atomicAdd(&accs[p*4+0], a0*inv);
    atomicAdd(&accs[p*4+1], a1*inv);
    atomicAdd(&accs[p*4+2], a2*inv);
    atomicAdd(&accs[p*4+3], a3*inv);
    __syncthreads();
    for (int i = tid; i < 196; i += 256) atomicAdd(&g_wstat[i], accs[i]);

    __threadfence();
    if (tid == 0) lastb = (atomicAdd(&g_ctr, 1) == (int)gridDim.x - 1);
    __syncthreads();
    if (!lastb) return;
    if (tid == 0) g_ctr = 0;

    float* kpad = buf;
    for (int i = tid; i < 49*196; i += 256) kpad[i] = 0.f;
    __syncthreads();
    if (tid < 49) {
        int p2 = tid;
        const float inv1024 = 1.f/1024.f;
        float wsx = g_wstat[p2*4+0]*inv1024;
        float wsy = g_wstat[p2*4+1]*inv1024;
        float wop = g_wstat[p2*4+2]*inv1024;
        float wr  = g_wstat[p2*4+3]*inv1024;
        wops[p2] = wop;
        float c00 = wsx*wsx + 1e-5f;
        float c11 = wsy*wsy + 1e-5f;
        float c01 = wr*wsx*wsy;
        float det = c00*c11 - c01*c01;
        float i00 = c11/det, i11 = c00/det, i01 = -c01/det;
        float norm = 1.f/(2.f*3.14159265358979f*sqrtf(det));
        float kv[25]; float kmx = 0.f;
        #pragma unroll
        for (int i = 0; i < 5; i++)
            #pragma unroll
            for (int j = 0; j < 5; j++) {
                float yv = -5.f + 2.5f*i;
                float xv = -5.f + 2.5f*j;
                float z = -0.5f*(i00*xv*xv + 2.f*i01*xv*yv + i11*yv*yv);
                float k = expf(z)*norm;
                kv[i*5+j] = k; kmx = fmaxf(kmx, k);
            }
        float im = 1.f/kmx;
        #pragma unroll
        for (int i = 0; i < 5; i++)
            #pragma unroll
            for (int j = 0; j < 5; j++)
                kpad[p2*196 + (i+4)*14 + (j+4)] = kv[i*5+j]*im;
    }
    __syncthreads();
    for (int idx = tid; idx < 49*196; idx += 256) {
        int p2 = idx/196, hw = idx%196, h = hw/14, w = hw%14;
        float txo = (0.5f - (float)(p2/7)*(1.f/7.f))*2.f;
        float tyo = (0.5f - (float)(p2%7)*(1.f/7.f))*2.f;
        float gxv = -1.f + (2.f/13.f)*w + txo;
        float gyv = -1.f + (2.f/13.f)*h + tyo;
        float px = (gxv + 1.f)*0.5f*13.f;
        float py = (gyv + 1.f)*0.5f*13.f;
        float x0f = floorf(px), y0f = floorf(py);
        int x0 = (int)x0f, y0 = (int)y0f;
        float wx = px - x0f, wy = py - y0f;
        float s00 = (y0   >= 0 && y0   < 14 && x0   >= 0 && x0   < 14) ? kpad[p2*196 + y0*14 + x0]       : 0.f;
        float s01 = (y0   >= 0 && y0   < 14 && x0+1 >= 0 && x0+1 < 14) ? kpad[p2*196 + y0*14 + x0+1]     : 0.f;
        float s10 = (y0+1 >= 0 && y0+1 < 14 && x0   >= 0 && x0   < 14) ? kpad[p2*196 + (y0+1)*14 + x0]   : 0.f;
        float s11 = (y0+1 >= 0 && y0+1 < 14 && x0+1 >= 0 && x0+1 < 14) ? kpad[p2*196 + (y0+1)*14 + x0+1] : 0.f;
        float kt = s00*(1.f-wy)*(1.f-wx) + s01*(1.f-wy)*wx + s10*wy*(1.f-wx) + s11*wy*wx;
        g_ktw[idx] = kt * wops[p2];
    }
}

// ------- splat -> NHWC fp16 (392 thr, half/thread) + pack conv224 weights -----
#define SPLAT_SMEM ((49*196 + 49*64)*4)
__global__ void splat(const float* __restrict__ feat,
                      const float* __restrict__ wc, const float* __restrict__ wf) {
    extern __shared__ float sm[];
    float* kts = sm;
    float* fp  = sm + 49*196;
    int bl = blockIdx.x;
    int b = bl / 256; int l = bl % 256; int pr = l / 16, pc = l % 16;
    int tid = threadIdx.x;   // 392

    for (int i = bl*392 + tid; i < 294912; i += 1024*392) {
        int ci = i & 63; int t = i >> 6;
        int co = t & 127; t >>= 7;
        int dydx = t % 9; t /= 9;
        int half = t & 1; int sel = t >> 1;
        const float* W = sel ? wf : wc;
        float v = W[(size_t)(half*128 + co)*576 + ci*9 + dydx];
        size_t base = ((size_t)((sel*2 + half)*9 + dydx))*16384;
        uint32_t off = (uint32_t)co*128 + (((uint32_t)(ci>>3)*16) ^ (((uint32_t)co&7)<<4)) + (ci&7)*2;
        *(__half*)(g_cw + base + off) = __float2half(v);
    }

    for (int i = tid; i < 49*196; i += 392) kts[i] = g_ktw[i];
    const float* fb = feat + (size_t)b*64*HH*HH;
    for (int i = tid; i < 49*64; i += 392) {
        int p = i >> 6, c = i & 63;
        fp[i] = fb[((size_t)c*HH + pr*7 + p/7)*HH + pc*7 + p%7];
    }
    __syncthreads();
    int half = tid / 196;
    int pix  = tid % 196;
    int h = pix/14, w = pix%14;
    int oy = pr*14 + h, ox = pc*14 + w;
    size_t pixb = ((size_t)b*H2 + oy)*H2 + ox;
    __half* gh = g_gfh + pixb*64 + half*32;
    float a[32];
    #pragma unroll
    for (int j = 0; j < 32; j++) a[j] = 0.f;
    for (int p = 0; p < 49; p++) {
        float k = kts[p*196 + pix];
        const float4* f4 = (const float4*)(fp + p*64 + half*32);
        #pragma unroll
        for (int j = 0; j < 8; j++) {
            float4 v = f4[j];
            a[j*4+0] += k*v.x; a[j*4+1] += k*v.y;
            a[j*4+2] += k*v.z; a[j*4+3] += k*v.w;
        }
    }
    #pragma unroll
    for (int j = 0; j < 32; j += 4) {
        *(__half2*)(gh + j)     = __floats2half2_rn(__saturatef(a[j]),   __saturatef(a[j+1]));
        *(__half2*)(gh + j + 2) = __floats2half2_rn(__saturatef(a[j+2]), __saturatef(a[j+3]));
    }
}

// ------- conv3x3 64->256 @224 via mma.sync (1-pass fp16, 3-buf pipeline) ------
#define CM_WBASE 41472
#define CM_WBUF  16384
#define CM_SMEM  (41472 + 3*16384)   // 90624

__global__ void __launch_bounds__(512, 1) conv224m(const float* __restrict__ bias_c,
                                                   const float* __restrict__ bias_f) {
    extern __shared__ __align__(16) char smc[];
    __shared__ float sbias[128];
    uint32_t sb;
    asm("{ .reg .u64 t; cvta.to.shared.u64 t, %1; cvt.u32.u64 %0, t; }" : "=r"(sb) : "l"(smc));
    int tid = threadIdx.x, wid = tid >> 5, lane = tid & 31;
    int bt = blockIdx.x, cohalf = blockIdx.y;
    int sel = blockIdx.z & 1, b = blockIdx.z >> 1;
    int row0 = (bt/14)*16, col0 = (bt%14)*16;
    int wm = wid >> 1, wn = wid & 1;
    int nb = wn*64;

    int lr8  = lane & 7;
    int a_mh = (lane >> 3) & 1;
    int a_jh = (lane >> 4) & 1;
    int b_jh = (lane >> 3) & 1;
    int b_nh = (lane >> 4) & 1;

    const __half* gh = g_gfh + (size_t)b*H2*H2*64;
    const unsigned char* wsrc = g_cw + (size_t)(sel*2 + cohalf)*9*16384;
    const float* bias = sel ? bias_f : bias_c;

    // prologue: tap0 (group), tap1 (group), A halo (group)
    for (int i = tid; i < 1024; i += 512)
        cpa16(smc + CM_WBASE + i*16, wsrc + i*16);
    asm volatile("cp.async.commit_group;" ::: "memory");
    for (int i = tid; i < 1024; i += 512)
        cpa16(smc + CM_WBASE + CM_WBUF + i*16, wsrc + 16384 + i*16);
    asm volatile("cp.async.commit_group;" ::: "memory");
    for (int i = tid; i < 2592; i += 512) {
        int pos = i >> 3, j = i & 7;
        int r = pos / 18, c = pos - r*18;
        int gy = row0 + r - 1, gx = col0 + c - 1;
        int ok = (gy >= 0 && gy < H2 && gx >= 0 && gx < H2);
        const __half* src = gh + ((size_t)(ok ? gy : 0)*H2 + (ok ? gx : 0))*64 + j*8;
        cpa16z(smc + (r*18 + c)*128 + (((uint32_t)j*16) ^ (((uint32_t)c&7)<<4)), src, ok ? 16 : 0);
    }
    asm volatile("cp.async.commit_group;" ::: "memory");
    if (tid < 128) sbias[tid] = bias[cohalf*128 + tid];

    float acc[2][8][4];
    #pragma unroll
    for (int t = 0; t < 2; t++)
        #pragma unroll
        for (int u = 0; u < 8; u++)
            #pragma unroll
            for (int j = 0; j < 4; j++) acc[t][u][j] = 0.f;

    uint32_t bRowOff = (uint32_t)((nb + b_nh*8 + lr8)*128);
    uint32_t swB = (uint32_t)(lr8 << 4);

    for (int dydx = 0; dydx < 9; dydx++) {
        if (dydx + 2 <= 8) {
            int tapN = dydx + 2;
            const unsigned char* src = wsrc + (size_t)tapN*16384;
            char* dst = smc + CM_WBASE + (tapN % 3)*CM_WBUF;
            for (int i = tid; i < 1024; i += 512)
                cpa16(dst + i*16, src + i*16);
            asm volatile("cp.async.commit_group;" ::: "memory");
        }
        if (dydx == 0)      asm volatile("cp.async.wait_group 1;" ::: "memory");
        else if (dydx <= 6) asm volatile("cp.async.wait_group 2;" ::: "memory");
        else if (dydx == 7) asm volatile("cp.async.wait_group 1;" ::: "memory");
        else                asm volatile("cp.async.wait_group 0;" ::: "memory");
        __syncthreads();

        int dy = dydx/3, dx = dydx - dy*3;
        uint32_t wb = sb + CM_WBASE + (uint32_t)((dydx % 3)*CM_WBUF) + bRowOff;

        int cA = dx + lr8 + a_mh*8;
        uint32_t swA = (uint32_t)(((dx + lr8) & 7) << 4);
        uint32_t aBase0 = sb + (uint32_t)((((wm*2 + dy)*18 + cA))*128);
        uint32_t aBase1 = aBase0 + 18*128;

        #pragma unroll
        for (int ks = 0; ks < 4; ks++) {
            uint32_t ka = (uint32_t)(((ks*2 + a_jh)*16)) ^ swA;
            uint32_t a0[4], a1[4];
            ldsm4(a0[0], a0[1], a0[2], a0[3], aBase0 + ka);
            ldsm4(a1[0], a1[1], a1[2], a1[3], aBase1 + ka);
            uint32_t kb = (uint32_t)(((ks*2 + b_jh)*16)) ^ swB;
            #pragma unroll
            for (int up = 0; up < 4; up++) {
                uint32_t br[4];
                ldsm4(br[0], br[1], br[2], br[3], wb + (uint32_t)(up*2048) + kb);
                mma16816(acc[0][2*up],   a0[0], a0[1], a0[2], a0[3], br[0], br[1]);
                mma16816(acc[0][2*up+1], a0[0], a0[1], a0[2], a0[3], br[2], br[3]);
                mma16816(acc[1][2*up],   a1[0], a1[1], a1[2], a1[3], br[0], br[1]);
                mma16816(acc[1][2*up+1], a1[0], a1[1], a1[2], a1[3], br[2], br[3]);
            }
        }
        __syncthreads();
    }

    int egrp = lane >> 2, et4 = lane & 3;
    __half* outp = sel ? g_freqh : g_coefh;
    #pragma unroll
    for (int t = 0; t < 2; t++) {
        int gy = row0 + wm*2 + t;
        #pragma unroll
        for (int u = 0; u < 8; u++) {
            int cidx = nb + u*8 + et4*2;
            float b0 = sbias[cidx], b1 = sbias[cidx+1];
            size_t o0 = (((size_t)b*H2 + gy)*H2 + col0 + egrp)*256 + cohalf*128 + cidx;
            size_t o1 = o0 + (size_t)8*256;
            *(__half2*)&outp[o0] = __floats2half2_rn(acc[t][u][0] + b0, acc[t][u][1] + b1);
            *(__half2*)&outp[o1] = __floats2half2_rn(acc[t][u][2] + b0, acc[t][u][3] + b1);
        }
    }
}

// ---------------- gather + fourier basis -> X0 fp16 (+ zero out) --------------
__global__ void gather_basis(const float* __restrict__ coord,
                             const float* __restrict__ cell,
                             const float* __restrict__ phase_w,
                             float* __restrict__ outz) {
    int gid = blockIdx.x*256 + threadIdx.x;
    if (gid < MTOT*3) outz[gid] = 0.f;
    int warp = threadIdx.x / 32, lane = threadIdx.x % 32;
    int m = blockIdx.x * 8 + warp;
    int b = m / QQ; int q = m % QQ;
    float cy = coord[((size_t)b*QQ + q)*2 + 0];
    float cx = coord[((size_t)b*QQ + q)*2 + 1];
    int ix = (int)rintf(((cx + 1.f)*(float)H2 - 1.f)*0.5f);
    int iy = (int)rintf(((cy + 1.f)*(float)H2 - 1.f)*0.5f);
    bool ok = (ix >= 0 && ix < H2 && iy >= 0 && iy < H2);
    __half* xh = g_X0h + (size_t)m*HID;
    if (!ok) {
        __half z = __float2half(0.f);
        #pragma unroll
        for (int kk = 0; kk < 4; kk++) {
            int k = lane + kk*32;
            xh[k] = z; xh[128+k] = z;
        }
        return;
    }
    float fcy = -1.f + 1.f/(float)H2 + (2.f/(float)H2)*(float)iy;
    float fcx = -1.f + 1.f/(float)H2 + (2.f/(float)H2)*(float)ix;
    float rely = (cy - fcy)*(float)H2;
    float relx = (cx - fcx)*(float)H2;
    float rc0 = cell[((size_t)b*QQ + q)*2 + 0]*(float)H2;
    float rc1 = cell[((size_t)b*QQ + q)*2 + 1]*(float)H2;
    size_t base = (((size_t)b*H2 + iy)*H2 + ix)*HID;
    const __half*  cf = g_coefh + base;
    const __half2* fq = (const __half2*)(g_freqh + base);
    const float2* pw = (const float2*)phase_w;
    const float PI = 3.14159265358979f;
    #pragma unroll
    for (int kk = 0; kk < 4; kk++) {
        int k = lane + kk*32;
        float2 f = __half22float2(fq[k]);
        float2 p = pw[k];
        float s = (f.x*rely + f.y*relx + rc0*p.x + rc1*p.y) * PI;
        xh[k]     = __float2half(__half2float(cf[k])       * __cosf(s));
        xh[128+k] = __float2half(__half2float(cf[128 + k]) * __sinf(s));
    }
}

// ---------------- mma.sync fp16 GEMM (1-pass + ldmatrix) ----------------------
#define GM_BB 0
#define GM_AB 65536
#define GM_SMEM (65536 + 2*16384)

__global__ void __launch_bounds__(256, 1) gemm_mma(const float* __restrict__ bias, int layer,
                                                   const float* __restrict__ w3,
                                                   const float* __restrict__ b3,
                                                   float* __restrict__ out) {
    extern __shared__ __align__(16) char smc[];
    __shared__ float sbias[128];
    __shared__ float w3s[3*128];
    uint32_t sb;
    asm("{ .reg .u64 t; cvta.to.shared.u64 t, %1; cvt.u32.u64 %0, t; }" : "=r"(sb) : "l"(smc));
    int tid = threadIdx.x, wid = tid >> 5, lane = tid & 31;
    int m0 = blockIdx.x * 128;
    int n0 = blockIdx.y * 128;
    int wm = wid >> 1, wn = wid & 1;
    int mb = wm * 32, nb = wn * 64;

    int lr8  = lane & 7;
    int a_mh = (lane >> 3) & 1;
    int a_jh = (lane >> 4) & 1;
    int b_jh = (lane >> 3) & 1;
    int b_nh = (lane >> 4) & 1;

    const __half* Ah = layer ? g_X1h : g_X0h;
    const __half* Wh = g_Wh[layer];

    for (int i = tid; i < 4096; i += 256) {
        int n = i >> 5; int j = i & 31;
        const __half* src = Wh + (size_t)(n0 + n)*256 + j*8;
        cpa16(smc + GM_BB + n*512 + ((j*16) ^ ((n&7)<<4)), src);
    }
    for (int i = tid; i < 1024; i += 256) {
        int m = i >> 3; int j = i & 7;
        const __half* src = Ah + (size_t)(m0 + m)*256 + j*8;
        cpa16(smc + GM_AB + m*128 + ((j*16) ^ ((m&7)<<4)), src);
    }
    asm volatile("cp.async.commit_group;" ::: "memory");
    if (tid < 128) {
        sbias[tid] = bias[n0 + tid];
        if (layer) {
            w3s[tid]       = w3[0*256 + n0 + tid];
            w3s[128 + tid] = w3[1*256 + n0 + tid];
            w3s[256 + tid] = w3[2*256 + n0 + tid];
        }
    }

    float acc[2][8][4];
    #pragma unroll
    for (int t = 0; t < 2; t++)
        #pragma unroll
        for (int u = 0; u < 8; u++)
            #pragma unroll
            for (int j = 0; j < 4; j++) acc[t][u][j] = 0.f;

    uint32_t aRowOff = (uint32_t)((a_mh*8 + lr8)*128);
    uint32_t swA = (uint32_t)(lr8 << 4);
    uint32_t bRowOff = (uint32_t)((nb + b_nh*8 + lr8)*512);
    uint32_t swB = swA;
    uint32_t bB = sb + GM_BB + bRowOff;

    for (int c = 0; c < 4; c++) {
        if (c < 3) {
            int cn = c + 1;
            char* dstb = smc + GM_AB + (cn & 1)*16384;
            for (int i = tid; i < 1024; i += 256) {
                int m = i >> 3; int j = i & 7;
                const __half* src = Ah + (size_t)(m0 + m)*256 + cn*64 + j*8;
                cpa16(dstb + m*128 + ((j*16) ^ ((m&7)<<4)), src);
            }
            asm volatile("cp.async.commit_group;" ::: "memory");
            asm volatile("cp.async.wait_group 1;" ::: "memory");
        } else {
            asm volatile("cp.async.wait_group 0;" ::: "memory");
        }
        __syncthreads();

        uint32_t bA = sb + GM_AB + (c & 1)*16384 + aRowOff;
        #pragma unroll
        for (int ks = 0; ks < 4; ks++) {
            uint32_t ka = (uint32_t)(((ks*2 + a_jh)*16)) ^ swA;
            uint32_t a0[4], a1[4];
            ldsm4(a0[0], a0[1], a0[2], a0[3], bA + (uint32_t)(mb*128) + ka);
            ldsm4(a1[0], a1[1], a1[2], a1[3], bA + (uint32_t)((mb+16)*128) + ka);
            uint32_t kb = (uint32_t)(((c*8 + ks*2 + b_jh)*16)) ^ swB;
            #pragma unroll
            for (int up = 0; up < 4; up++) {
                uint32_t br[4];
                ldsm4(br[0], br[1], br[2], br[3], bB + (uint32_t)(up*8192) + kb);
                mma16816(acc[0][2*up],   a0[0], a0[1], a0[2], a0[3], br[0], br[1]);
                mma16816(acc[0][2*up+1], a0[0], a0[1], a0[2], a0[3], br[2], br[3]);
                mma16816(acc[1][2*up],   a1[0], a1[1], a1[2], a1[3], br[0], br[1]);
                mma16816(acc[1][2*up+1], a1[0], a1[1], a1[2], a1[3], br[2], br[3]);
            }
        }
        __syncthreads();
    }

    int grp = lane >> 2, t4 = lane & 3;
    if (layer == 0) {
        #pragma unroll
        for (int t = 0; t < 2; t++) {
            int r0 = m0 + mb + t*16 + grp;
            int r1 = r0 + 8;
            #pragma unroll
            for (int u = 0; u < 8; u++) {
                int cb = nb + u*8 + t4*2;
                float b0v = sbias[cb], b1v = sbias[cb+1];
                float v00 = fmaxf(acc[t][u][0] + b0v, 0.f);
                float v01 = fmaxf(acc[t][u][1] + b1v, 0.f);
                float v10 = fmaxf(acc[t][u][2] + b0v, 0.f);
                float v11 = fmaxf(acc[t][u][3] + b1v, 0.f);
                int gcol = n0 + cb;
                *(__half2*)&g_X1h[(size_t)r0*256 + gcol] = __floats2half2_rn(v00, v01);
                *(__half2*)&g_X1h[(size_t)r1*256 + gcol] = __floats2half2_rn(v10, v11);
            }
        }
    } else {
        #pragma unroll
        for (int t = 0; t < 2; t++) {
            int r0 = m0 + mb + t*16 + grp;
            int r1 = r0 + 8;
            float p0[3] = {0.f, 0.f, 0.f};
            float p1[3] = {0.f, 0.f, 0.f};
            #pragma unroll
            for (int u = 0; u < 8; u++) {
                int cb = nb + u*8 + t4*2;
                float b0v = sbias[cb], b1v = sbias[cb+1];
                float v00 = fmaxf(acc[t][u][0] + b0v, 0.f);
                float v01 = fmaxf(acc[t][u][1] + b1v, 0.f);
                float v10 = fmaxf(acc[t][u][2] + b0v, 0.f);
                float v11 = fmaxf(acc[t][u][3] + b1v, 0.f);
                #pragma unroll
                for (int cc = 0; cc < 3; cc++) {
                    float w0 = w3s[cc*128 + cb], w1 = w3s[cc*128 + cb + 1];
                    p0[cc] += v00*w0 + v01*w1;
                    p1[cc] += v10*w0 + v11*w1;
                }
            }
            #pragma unroll
            for (int cc = 0; cc < 3; cc++) {
                p0[cc] += __shfl_xor_sync(0xffffffffu, p0[cc], 1);
                p0[cc] += __shfl_xor_sync(0xffffffffu, p0[cc], 2);
                p1[cc] += __shfl_xor_sync(0xffffffffu, p1[cc], 1);
                p1[cc] += __shfl_xor_sync(0xffffffffu, p1[cc], 2);
            }
            if (t4 == 0) {
                #pragma unroll
                for (int cc = 0; cc < 3; cc++) {
                    float bb = (n0 == 0) ? b3[cc] : 0.f;
                    atomicAdd(&out[(size_t)r0*3 + cc], p0[cc] + bb);
                    atomicAdd(&out[(size_t)r1*3 + cc], p1[cc] + bb);
                }
            }
        }
    }
}

// ---------------- launch -------------------------------------------------------
extern "C" void kernel_launch(void* const* d_in, const int* in_sizes, int n_in,
                              void* d_out, int out_size) {
    const float* feat    = (const float*)d_in[0];
    const float* coord   = (const float*)d_in[1];
    const float* cell    = (const float*)d_in[2];
    const float* cls_w1  = (const float*)d_in[3];
    const float* cls_b1  = (const float*)d_in[4];
    const float* cls_w2  = (const float*)d_in[5];
    const float* cls_b2  = (const float*)d_in[6];
    const float* sigma_x = (const float*)d_in[7];
    const float* sigma_y = (const float*)d_in[8];
    const float* opacity = (const float*)d_in[9];
    const float* rho     = (const float*)d_in[10];
    const float* coef_w  = (const float*)d_in[11];
    const float* coef_b  = (const float*)d_in[12];
    const float* freq_w  = (const float*)d_in[13];
    const float* freq_b  = (const float*)d_in[14];
    const float* phase_w = (const float*)d_in[15];
    const float* mlp_w1  = (const float*)d_in[16];
    const float* mlp_b1  = (const float*)d_in[17];
    const float* mlp_w2  = (const float*)d_in[18];
    const float* mlp_b2  = (const float*)d_in[19];
    const float* mlp_w3  = (const float*)d_in[20];
    const float* mlp_b3  = (const float*)d_in[21];
    float* out = (float*)d_out;

    cudaFuncSetAttribute(conv112t, cudaFuncAttributeMaxDynamicSharedMemorySize, C1_SMEM);
    cudaFuncSetAttribute(splat,    cudaFuncAttributeMaxDynamicSharedMemorySize, SPLAT_SMEM);
    cudaFuncSetAttribute(conv224m, cudaFuncAttributeMaxDynamicSharedMemorySize, CM_SMEM);
    cudaFuncSetAttribute(gemm_mma, cudaFuncAttributeMaxDynamicSharedMemorySize, GM_SMEM);

    feat_prep<<<12544, 256>>>(feat, cls_w1, mlp_w1, mlp_w2);                       // #1
    conv112t<<<dim3(49, 1, BB), 512, C1_SMEM>>>(cls_b1);                           // #2
    logits_stats<<<196, 256>>>(cls_w2, cls_b2, sigma_x, sigma_y, opacity, rho);    // #3
    splat<<<1024, 392, SPLAT_SMEM>>>(feat, coef_w, freq_w);                        // #4
    conv224m<<<dim3(196, 2, BB*2), 512, CM_SMEM>>>(coef_b, freq_b);                // #5
    gather_basis<<<MTOT/8, 256>>>(coord, cell, phase_w, out);                      // #6
    gemm_mma<<<dim3(MTOT/128, 2), 256, GM_SMEM>>>(mlp_b1, 0, mlp_w3, mlp_b3, out); // #7
    gemm_mma<<<dim3(MTOT/128, 2), 256, GM_SMEM>>>(mlp_b2, 1, mlp_w3, mlp_b3, out); // #8
}